// round 5
// baseline (speedup 1.0000x reference)
#include <cuda_runtime.h>
#include <cstdint>

// Problem constants (B=64, T=128, N=128, K_SUP=8, E=512, steps=10)
#define M_ROWS   8192          // B*T
#define EDIM     512
#define G4       2048          // 4*E
#define NKS      1024          // N*K_SUP
#define NBATCH   64
#define NSTEPS   10

// ---------------- scratch (device globals; no allocation allowed) ------------
__device__ float g_xW[(size_t)M_ROWS * G4];        // 64 MB
__device__ float g_gates[(size_t)M_ROWS * G4];     // 64 MB
__device__ float g_h[(size_t)M_ROWS * EDIM];       // 16 MB
__device__ float g_c[(size_t)M_ROWS * EDIM];       // 16 MB
__device__ float g_scores[(size_t)M_ROWS * NKS];   // 32 MB
__device__ float g_r[(size_t)M_ROWS * EDIM];       // 16 MB
// tf32 hi/lo split operand buffers
__device__ float g_hH[(size_t)M_ROWS * EDIM],  g_hL[(size_t)M_ROWS * EDIM];
__device__ float g_scH[(size_t)M_ROWS * NKS],  g_scL[(size_t)M_ROWS * NKS];
__device__ float g_tgtH[(size_t)M_ROWS * EDIM], g_tgtL[(size_t)M_ROWS * EDIM];
__device__ float g_WihH[(size_t)G4 * EDIM],    g_WihL[(size_t)G4 * EDIM];
__device__ float g_WhhH[(size_t)G4 * EDIM],    g_WhhL[(size_t)G4 * EDIM];
__device__ float g_supH[(size_t)NBATCH * NKS * EDIM], g_supL[(size_t)NBATCH * NKS * EDIM];
__device__ float g_supTH[(size_t)NBATCH * EDIM * NKS], g_supTL[(size_t)NBATCH * EDIM * NKS];

// ---------------- tf32 split helpers -----------------------------------------
__device__ __forceinline__ float f2tf32f(float x) {
    uint32_t r;
    asm("cvt.rna.tf32.f32 %0, %1;" : "=r"(r) : "f"(x));
    return __uint_as_float(r);
}
__device__ __forceinline__ void split2(float x, float& hi, float& lo) {
    hi = f2tf32f(x);
    lo = f2tf32f(x - hi);
}

// elementwise split: in -> hi/lo (tf32 bit patterns stored as float)
__global__ void split_kernel(const float4* __restrict__ in,
                             float4* __restrict__ hi, float4* __restrict__ lo)
{
    long long i = (long long)blockIdx.x * blockDim.x + threadIdx.x;
    float4 v = in[i];
    float4 h, l;
    split2(v.x, h.x, l.x); split2(v.y, h.y, l.y);
    split2(v.z, h.z, l.z); split2(v.w, h.w, l.w);
    hi[i] = h; lo[i] = l;
}

// sup[b][n][e] -> supT[b][e][n], split into hi/lo
__global__ void transpose_split(const float* __restrict__ sup,
                                float* __restrict__ th, float* __restrict__ tl)
{
    __shared__ float t[32][33];
    int b = blockIdx.z;
    int e0 = blockIdx.x * 32, n0 = blockIdx.y * 32;
    const float* S = sup + (size_t)b * NKS * EDIM;
    #pragma unroll
    for (int j = 0; j < 4; j++)
        t[threadIdx.y + j * 8][threadIdx.x] =
            S[(size_t)(n0 + threadIdx.y + j * 8) * EDIM + e0 + threadIdx.x];
    __syncthreads();
    float* TH = th + (size_t)b * EDIM * NKS;
    float* TL = tl + (size_t)b * EDIM * NKS;
    #pragma unroll
    for (int j = 0; j < 4; j++) {
        float v = t[threadIdx.x][threadIdx.y + j * 8];
        float h, l; split2(v, h, l);
        size_t o = (size_t)(e0 + threadIdx.y + j * 8) * NKS + n0 + threadIdx.x;
        TH[o] = h; TL[o] = l;
    }
}

// ---------------- 3xTF32 NT GEMM, cp.async 4-stage pipeline -------------------
// C[m,n] = sum_k A[m,k]*B[n,k]  (+Cadd) (+bias1+bias2), 3-term hi/lo split.
// Operands are PRE-SPLIT tf32 hi/lo arrays (k-contiguous, both A and B).
// Block tile 128x128x16, 256 threads, warp tile 64x32, m16n8k8 tf32 mma.
#define BM 128
#define BN 128
#define BK 16
#define LDS_ 20                 // padded row stride (u32)
#define STG 4
#define TILE_U32 (BM * LDS_)    // 2560 u32 per matrix tile
#define TILE_B   (TILE_U32 * 4) // 10240 bytes
#define SMEM_SZ  (4 * STG * TILE_B)  // 163840 bytes

__device__ __forceinline__ void cpa16(uint32_t dst, const float* src) {
    asm volatile("cp.async.cg.shared.global [%0], [%1], 16;\n"
                 :: "r"(dst), "l"(src));
}

#define MMA_TF32(c, a0, a1, a2, a3, b0, b1)                                     \
    asm volatile(                                                               \
        "mma.sync.aligned.m16n8k8.row.col.f32.tf32.tf32.f32 "                   \
        "{%0,%1,%2,%3}, {%4,%5,%6,%7}, {%8,%9}, {%0,%1,%2,%3};"                 \
        : "+f"((c)[0]), "+f"((c)[1]), "+f"((c)[2]), "+f"((c)[3])                \
        : "r"(a0), "r"(a1), "r"(a2), "r"(a3), "r"(b0), "r"(b1))

__global__ __launch_bounds__(256, 1)
void gemm_nt(const float* __restrict__ AH, const float* __restrict__ AL,
             const float* __restrict__ BH, const float* __restrict__ BL,
             float* __restrict__ C, const float* __restrict__ Cadd,
             const float* __restrict__ bias1, const float* __restrict__ bias2,
             int N, int K,
             long long aB, long long bB, long long cB)
{
    extern __shared__ uint32_t smem[];
    const uint32_t ubase = (uint32_t)__cvta_generic_to_shared(smem);

    const int tid = threadIdx.x;
    const int bx = blockIdx.x, by = blockIdx.y, bz = blockIdx.z;
    const int lane = tid & 31;
    const int w  = tid >> 5;
    const int wr = w >> 2;               // 0..1
    const int wc = w & 3;                // 0..3
    const int g1 = lane >> 2;            // 0..7
    const int g2 = lane & 3;             // 0..3

    const long long aOff = (long long)bz * aB + (long long)by * BM * K;
    const long long bOff = (long long)bz * bB + (long long)bx * BN * K;
    AH += aOff; AL += aOff; BH += bOff; BL += bOff;
    C += (long long)bz * cB;

    // per-thread load coords (2 float4 slots per matrix per stage)
    const int f0 = tid, f1 = tid + 256;
    const int r0 = f0 >> 2, kg0 = (f0 & 3) * 4;
    const int r1 = f1 >> 2, kg1 = (f1 & 3) * 4;
    const uint32_t o0 = (uint32_t)(r0 * LDS_ + kg0) * 4;
    const uint32_t o1 = (uint32_t)(r1 * LDS_ + kg1) * 4;

    auto issue = [&](int stage, int k0) {
        const uint32_t uAH = ubase + stage * TILE_B;
        const uint32_t uAL = ubase + (STG + stage) * TILE_B;
        const uint32_t uBH = ubase + (2 * STG + stage) * TILE_B;
        const uint32_t uBL = ubase + (3 * STG + stage) * TILE_B;
        long long ga0 = (long long)r0 * K + k0 + kg0;
        long long ga1 = (long long)r1 * K + k0 + kg1;
        cpa16(uAH + o0, AH + ga0); cpa16(uAH + o1, AH + ga1);
        cpa16(uAL + o0, AL + ga0); cpa16(uAL + o1, AL + ga1);
        cpa16(uBH + o0, BH + ga0); cpa16(uBH + o1, BH + ga1);
        cpa16(uBL + o0, BL + ga0); cpa16(uBL + o1, BL + ga1);
    };

    float acc[4][4][4];
    #pragma unroll
    for (int i = 0; i < 4; i++)
        #pragma unroll
        for (int j = 0; j < 4; j++)
            #pragma unroll
            for (int q = 0; q < 4; q++) acc[i][j][q] = 0.f;

    const int KT = K / BK;

    // prime STG-1 stages
    #pragma unroll
    for (int s = 0; s < STG - 1; s++) {
        if (s < KT) issue(s, s * BK);
        asm volatile("cp.async.commit_group;\n");
    }

    for (int kt = 0; kt < KT; kt++) {
        asm volatile("cp.async.wait_group %0;\n" :: "n"(STG - 2));
        __syncthreads();

        int pf = kt + STG - 1;
        if (pf < KT) issue(pf & (STG - 1), pf * BK);
        asm volatile("cp.async.commit_group;\n");

        const int stage = kt & (STG - 1);
        const uint32_t* sAH = smem + stage * TILE_U32;
        const uint32_t* sAL = smem + (STG + stage) * TILE_U32;
        const uint32_t* sBH = smem + (2 * STG + stage) * TILE_U32;
        const uint32_t* sBL = smem + (3 * STG + stage) * TILE_U32;

        #pragma unroll
        for (int ks = 0; ks < BK; ks += 8) {
            const int kk = ks + g2;
            uint32_t aH[4][4], aL[4][4], bH[4][2], bL[4][2];
            #pragma unroll
            for (int mt = 0; mt < 4; mt++) {
                int m0 = wr * 64 + mt * 16 + g1;
                int i00 = m0 * LDS_ + kk, i10 = (m0 + 8) * LDS_ + kk;
                aH[mt][0] = sAH[i00];     aH[mt][1] = sAH[i10];
                aH[mt][2] = sAH[i00 + 4]; aH[mt][3] = sAH[i10 + 4];
                aL[mt][0] = sAL[i00];     aL[mt][1] = sAL[i10];
                aL[mt][2] = sAL[i00 + 4]; aL[mt][3] = sAL[i10 + 4];
            }
            #pragma unroll
            for (int nt = 0; nt < 4; nt++) {
                int n0 = (wc * 32 + nt * 8 + g1) * LDS_ + kk;
                bH[nt][0] = sBH[n0]; bH[nt][1] = sBH[n0 + 4];
                bL[nt][0] = sBL[n0]; bL[nt][1] = sBL[n0 + 4];
            }
            #pragma unroll
            for (int mt = 0; mt < 4; mt++)
                #pragma unroll
                for (int nt = 0; nt < 4; nt++) {
                    float* c = acc[mt][nt];
                    MMA_TF32(c, aH[mt][0], aH[mt][1], aH[mt][2], aH[mt][3],
                             bH[nt][0], bH[nt][1]);
                    MMA_TF32(c, aH[mt][0], aH[mt][1], aH[mt][2], aH[mt][3],
                             bL[nt][0], bL[nt][1]);
                    MMA_TF32(c, aL[mt][0], aL[mt][1], aL[mt][2], aL[mt][3],
                             bH[nt][0], bH[nt][1]);
                }
        }
        __syncthreads();
    }

    // ---- epilogue: fp32 adds, float2 stores ----
    const int gr0 = by * BM + wr * 64;
    const int gc0 = bx * BN + wc * 32;
    #pragma unroll
    for (int mt = 0; mt < 4; mt++) {
        #pragma unroll
        for (int nt = 0; nt < 4; nt++) {
            int row = gr0 + mt * 16 + g1;
            int col = gc0 + nt * 8 + 2 * g2;
            long long i0 = (long long)row * N + col;
            long long i1 = (long long)(row + 8) * N + col;
            float v0 = acc[mt][nt][0], v1 = acc[mt][nt][1];
            float v2 = acc[mt][nt][2], v3 = acc[mt][nt][3];
            if (Cadd) {
                float2 u0 = *(const float2*)(Cadd + i0);
                float2 u1 = *(const float2*)(Cadd + i1);
                v0 += u0.x; v1 += u0.y; v2 += u1.x; v3 += u1.y;
            }
            if (bias1) {
                float bb0 = bias1[col] + bias2[col];
                float bb1 = bias1[col + 1] + bias2[col + 1];
                v0 += bb0; v1 += bb1; v2 += bb0; v3 += bb1;
            }
            *(float2*)(C + i0) = make_float2(v0, v1);
            *(float2*)(C + i1) = make_float2(v2, v3);
        }
    }
}

// ---------------- softmax over rows of 1024, writes tf32 hi/lo ---------------
__global__ void softmax1024_split(const float* __restrict__ s,
                                  float* __restrict__ oh, float* __restrict__ ol)
{
    __shared__ float red[8];
    const float* p = s + (size_t)blockIdx.x * NKS;
    float* ph = oh + (size_t)blockIdx.x * NKS;
    float* pl = ol + (size_t)blockIdx.x * NKS;
    const int tid = threadIdx.x;

    float v[4];
    float m = -1e30f;
    #pragma unroll
    for (int i = 0; i < 4; i++) { v[i] = p[tid + i * 256]; m = fmaxf(m, v[i]); }
    #pragma unroll
    for (int o = 16; o > 0; o >>= 1) m = fmaxf(m, __shfl_xor_sync(0xffffffffu, m, o));
    if ((tid & 31) == 0) red[tid >> 5] = m;
    __syncthreads();
    float bm = -1e30f;
    #pragma unroll
    for (int i = 0; i < 8; i++) bm = fmaxf(bm, red[i]);
    __syncthreads();

    float sum = 0.f;
    #pragma unroll
    for (int i = 0; i < 4; i++) { v[i] = __expf(v[i] - bm); sum += v[i]; }
    #pragma unroll
    for (int o = 16; o > 0; o >>= 1) sum += __shfl_xor_sync(0xffffffffu, sum, o);
    if ((tid & 31) == 0) red[tid >> 5] = sum;
    __syncthreads();
    float tot = 0.f;
    #pragma unroll
    for (int i = 0; i < 8; i++) tot += red[i];
    float inv = 1.f / tot;
    #pragma unroll
    for (int i = 0; i < 4; i++) {
        float a = v[i] * inv;
        float h, l; split2(a, h, l);
        ph[tid + i * 256] = h;
        pl[tid + i * 256] = l;
    }
}

// ---------------- fused LSTM pointwise (writes h + split) --------------------
__global__ void lstm_pw(const float* __restrict__ gates, const float* __restrict__ x,
                        const float* __restrict__ r, float* __restrict__ h,
                        float* __restrict__ c,
                        float* __restrict__ hH, float* __restrict__ hL)
{
    long long idx = (long long)blockIdx.x * blockDim.x + threadIdx.x;
    int m = (int)(idx >> 9);
    int e = (int)(idx & 511);
    const float* grow = gates + (long long)m * G4;
    float gi = grow[e];
    float gf = grow[512 + e];
    float gg = grow[1024 + e];
    float go = grow[1536 + e];
    float cp = c[idx];
    float si = 1.f / (1.f + __expf(-gi));
    float sf = 1.f / (1.f + __expf(-gf));
    float so = 1.f / (1.f + __expf(-go));
    float cn = sf * cp + si * tanhf(gg);
    float hn = so * tanhf(cn) + x[idx] + r[idx];
    c[idx] = cn;
    h[idx] = hn;
    float hh, hl; split2(hn, hh, hl);
    hH[idx] = hh;
    hL[idx] = hl;
}

// ---------------- launch ----------------------------------------------------
extern "C" void kernel_launch(void* const* d_in, const int* in_sizes, int n_in,
                              void* d_out, int out_size)
{
    const float* targets = (const float*)d_in[0];   // [8192, 512]
    const float* sup     = (const float*)d_in[1];   // [64, 1024, 512]
    const float* W_ih    = (const float*)d_in[2];   // [2048, 512]
    const float* W_hh    = (const float*)d_in[3];   // [2048, 512]
    const float* b_ih    = (const float*)d_in[4];   // [2048]
    const float* b_hh    = (const float*)d_in[5];   // [2048]
    float* out = (float*)d_out;

    float *xW, *gates, *h, *c, *scores, *r;
    float *hH, *hL, *scH, *scL, *tgtH, *tgtL;
    float *WihH, *WihL, *WhhH, *WhhL, *supH, *supL, *supTH, *supTL;
    cudaGetSymbolAddress((void**)&xW, g_xW);
    cudaGetSymbolAddress((void**)&gates, g_gates);
    cudaGetSymbolAddress((void**)&h, g_h);
    cudaGetSymbolAddress((void**)&c, g_c);
    cudaGetSymbolAddress((void**)&scores, g_scores);
    cudaGetSymbolAddress((void**)&r, g_r);
    cudaGetSymbolAddress((void**)&hH, g_hH);
    cudaGetSymbolAddress((void**)&hL, g_hL);
    cudaGetSymbolAddress((void**)&scH, g_scH);
    cudaGetSymbolAddress((void**)&scL, g_scL);
    cudaGetSymbolAddress((void**)&tgtH, g_tgtH);
    cudaGetSymbolAddress((void**)&tgtL, g_tgtL);
    cudaGetSymbolAddress((void**)&WihH, g_WihH);
    cudaGetSymbolAddress((void**)&WihL, g_WihL);
    cudaGetSymbolAddress((void**)&WhhH, g_WhhH);
    cudaGetSymbolAddress((void**)&WhhL, g_WhhL);
    cudaGetSymbolAddress((void**)&supH, g_supH);
    cudaGetSymbolAddress((void**)&supL, g_supL);
    cudaGetSymbolAddress((void**)&supTH, g_supTH);
    cudaGetSymbolAddress((void**)&supTL, g_supTL);

    cudaFuncSetAttribute(gemm_nt, cudaFuncAttributeMaxDynamicSharedMemorySize, SMEM_SZ);

    cudaMemsetAsync(h,  0, (size_t)M_ROWS * EDIM * sizeof(float));
    cudaMemsetAsync(c,  0, (size_t)M_ROWS * EDIM * sizeof(float));
    cudaMemsetAsync(hH, 0, (size_t)M_ROWS * EDIM * sizeof(float));
    cudaMemsetAsync(hL, 0, (size_t)M_ROWS * EDIM * sizeof(float));

    dim3 blk(256);

    // one-time operand splits
    split_kernel<<<(M_ROWS * EDIM / 4) / 256, 256>>>(
        (const float4*)targets, (float4*)tgtH, (float4*)tgtL);
    split_kernel<<<(G4 * EDIM / 4) / 256, 256>>>(
        (const float4*)W_ih, (float4*)WihH, (float4*)WihL);
    split_kernel<<<(G4 * EDIM / 4) / 256, 256>>>(
        (const float4*)W_hh, (float4*)WhhH, (float4*)WhhL);
    split_kernel<<<((size_t)NBATCH * NKS * EDIM / 4) / 256, 256>>>(
        (const float4*)sup, (float4*)supH, (float4*)supL);
    transpose_split<<<dim3(EDIM / 32, NKS / 32, NBATCH), dim3(32, 8)>>>(
        sup, supTH, supTL);

    // xW = x @ W_ih^T + b_ih + b_hh   (loop-invariant)
    gemm_nt<<<dim3(G4 / BN, M_ROWS / BM, 1), blk, SMEM_SZ>>>(
        tgtH, tgtL, WihH, WihL, xW, nullptr, b_ih, b_hh,
        G4, EDIM, 0, 0, 0);

    for (int s = 0; s < NSTEPS; s++) {
        // gates = xW + h_prev @ W_hh^T
        gemm_nt<<<dim3(G4 / BN, M_ROWS / BM, 1), blk, SMEM_SZ>>>(
            hH, hL, WhhH, WhhL, gates, xW, nullptr, nullptr,
            G4, EDIM, 0, 0, 0);

        // scores[b] = h_prev[b] @ sup[b]^T   (batched NT)
        gemm_nt<<<dim3(NKS / BN, 1, NBATCH), blk, SMEM_SZ>>>(
            hH, hL, supH, supL, scores, nullptr, nullptr, nullptr,
            NKS, EDIM,
            (long long)128 * EDIM, (long long)NKS * EDIM, (long long)128 * NKS);

        // softmax -> split attn
        softmax1024_split<<<M_ROWS, 256>>>(scores, scH, scL);

        // r[b] = attn[b] @ supT[b]^T  (NT with B = supT: rows e, k = n)
        gemm_nt<<<dim3(EDIM / BN, 1, NBATCH), blk, SMEM_SZ>>>(
            scH, scL, supTH, supTL, r, nullptr, nullptr, nullptr,
            EDIM, NKS,
            (long long)128 * NKS, (long long)EDIM * NKS, (long long)128 * EDIM);

        // pointwise LSTM cell + residual adds (+ h split for next step)
        lstm_pw<<<(M_ROWS * EDIM) / 256, 256>>>(gates, targets, r, h, c, hH, hL);
    }

    cudaMemcpyAsync(out, h, (size_t)M_ROWS * EDIM * sizeof(float),
                    cudaMemcpyDeviceToDevice);
}

// round 6
// speedup vs baseline: 1.8276x; 1.8276x over previous
#include <cuda_runtime.h>
#include <cstdint>

// Problem constants (B=64, T=128, N=128, K_SUP=8, E=512, steps=10)
#define M_ROWS   8192          // B*T
#define EDIM     512
#define G4       2048          // 4*E
#define NKS      1024          // N*K_SUP
#define NBATCH   64
#define NSTEPS   10

// ---------------- scratch (device globals; no allocation allowed) ------------
__device__ float g_xW[(size_t)M_ROWS * G4];        // 64 MB
__device__ float g_gates[(size_t)M_ROWS * G4];     // 64 MB
__device__ float g_h[(size_t)M_ROWS * EDIM];       // 16 MB
__device__ float g_c[(size_t)M_ROWS * EDIM];       // 16 MB
__device__ float g_scores[(size_t)M_ROWS * NKS];   // 32 MB
__device__ float g_r[(size_t)M_ROWS * EDIM];       // 16 MB
__device__ float g_rmean[(size_t)NBATCH * EDIM];   // step-0 uniform-attention read
// tf32 hi/lo split operand buffers
__device__ float g_hH[(size_t)M_ROWS * EDIM],  g_hL[(size_t)M_ROWS * EDIM];
__device__ float g_scH[(size_t)M_ROWS * NKS],  g_scL[(size_t)M_ROWS * NKS];
__device__ float g_tgtH[(size_t)M_ROWS * EDIM], g_tgtL[(size_t)M_ROWS * EDIM];
__device__ float g_WihH[(size_t)G4 * EDIM],    g_WihL[(size_t)G4 * EDIM];
__device__ float g_WhhH[(size_t)G4 * EDIM],    g_WhhL[(size_t)G4 * EDIM];
__device__ float g_supH[(size_t)NBATCH * NKS * EDIM], g_supL[(size_t)NBATCH * NKS * EDIM];
__device__ float g_supTH[(size_t)NBATCH * EDIM * NKS], g_supTL[(size_t)NBATCH * EDIM * NKS];

// ---------------- tf32 split helpers -----------------------------------------
__device__ __forceinline__ float f2tf32f(float x) {
    uint32_t r;
    asm("cvt.rna.tf32.f32 %0, %1;" : "=r"(r) : "f"(x));
    return __uint_as_float(r);
}
__device__ __forceinline__ void split2(float x, float& hi, float& lo) {
    hi = f2tf32f(x);
    lo = f2tf32f(x - hi);
}

// elementwise split: in -> hi/lo (tf32 bit patterns stored as float)
__global__ void split_kernel(const float4* __restrict__ in,
                             float4* __restrict__ hi, float4* __restrict__ lo)
{
    long long i = (long long)blockIdx.x * blockDim.x + threadIdx.x;
    float4 v = in[i];
    float4 h, l;
    split2(v.x, h.x, l.x); split2(v.y, h.y, l.y);
    split2(v.z, h.z, l.z); split2(v.w, h.w, l.w);
    hi[i] = h; lo[i] = l;
}

// sup[b][n][e] -> supT[b][e][n], split into hi/lo
__global__ void transpose_split(const float* __restrict__ sup,
                                float* __restrict__ th, float* __restrict__ tl)
{
    __shared__ float t[32][33];
    int b = blockIdx.z;
    int e0 = blockIdx.x * 32, n0 = blockIdx.y * 32;
    const float* S = sup + (size_t)b * NKS * EDIM;
    #pragma unroll
    for (int j = 0; j < 4; j++)
        t[threadIdx.y + j * 8][threadIdx.x] =
            S[(size_t)(n0 + threadIdx.y + j * 8) * EDIM + e0 + threadIdx.x];
    __syncthreads();
    float* TH = th + (size_t)b * EDIM * NKS;
    float* TL = tl + (size_t)b * EDIM * NKS;
    #pragma unroll
    for (int j = 0; j < 4; j++) {
        float v = t[threadIdx.x][threadIdx.y + j * 8];
        float h, l; split2(v, h, l);
        size_t o = (size_t)(e0 + threadIdx.y + j * 8) * NKS + n0 + threadIdx.x;
        TH[o] = h; TL[o] = l;
    }
}

// rmean[b][e] = (1/1024) * sum_{n,k} sup[b][n*k][e]
__global__ void sup_mean(const float* __restrict__ sup, float* __restrict__ rmean)
{
    __shared__ float4 part[128];
    const int b = blockIdx.x;
    const int c4 = threadIdx.x & 127;   // float4 column (128 = 512/4)
    const int half = threadIdx.x >> 7;  // rows [0,512) or [512,1024)
    const float4* S = (const float4*)(sup + (size_t)b * NKS * EDIM);
    float4 acc = make_float4(0.f, 0.f, 0.f, 0.f);
    for (int n = half * 512; n < half * 512 + 512; n++) {
        float4 v = S[(size_t)n * 128 + c4];
        acc.x += v.x; acc.y += v.y; acc.z += v.z; acc.w += v.w;
    }
    if (half) part[c4] = acc;
    __syncthreads();
    if (!half) {
        float4 o = part[c4];
        const float s = 1.f / 1024.f;
        ((float4*)rmean)[(size_t)b * 128 + c4] = make_float4(
            (acc.x + o.x) * s, (acc.y + o.y) * s, (acc.z + o.z) * s, (acc.w + o.w) * s);
    }
}

// ---------------- 3xTF32 NT GEMM, cp.async double buffer ----------------------
// C[m,n] = sum_k A[m,k]*B[n,k]  (+Cadd) (+bias1+bias2), 3-term hi/lo split.
// Operands are PRE-SPLIT tf32 hi/lo arrays (k-contiguous, both A and B).
// Block tile 128x128x16, 256 threads (8 warps), warp tile 64x32, m16n8k8 tf32.
// 2 stages x 4 tiles = 80KB dynamic smem -> 2 CTAs/SM, 16 warps.
#define BM 128
#define BN 128
#define BK 16
#define LDS_ 20                 // padded row stride (u32)
#define STG 2
#define TILE_U32 (BM * LDS_)    // 2560 u32 per matrix tile
#define TILE_B   (TILE_U32 * 4) // 10240 bytes
#define SMEM_SZ  (4 * STG * TILE_B)  // 81920 bytes

__device__ __forceinline__ void cpa16(uint32_t dst, const float* src) {
    asm volatile("cp.async.cg.shared.global [%0], [%1], 16;\n"
                 :: "r"(dst), "l"(src));
}

#define MMA_TF32(c, a0, a1, a2, a3, b0, b1)                                     \
    asm volatile(                                                               \
        "mma.sync.aligned.m16n8k8.row.col.f32.tf32.tf32.f32 "                   \
        "{%0,%1,%2,%3}, {%4,%5,%6,%7}, {%8,%9}, {%0,%1,%2,%3};"                 \
        : "+f"((c)[0]), "+f"((c)[1]), "+f"((c)[2]), "+f"((c)[3])                \
        : "r"(a0), "r"(a1), "r"(a2), "r"(a3), "r"(b0), "r"(b1))

__global__ __launch_bounds__(256, 2)
void gemm_nt(const float* __restrict__ AH, const float* __restrict__ AL,
             const float* __restrict__ BH, const float* __restrict__ BL,
             float* __restrict__ C, const float* __restrict__ Cadd,
             const float* __restrict__ bias1, const float* __restrict__ bias2,
             int N, int K,
             long long aB, long long bB, long long cB)
{
    extern __shared__ uint32_t smem[];
    const uint32_t ubase = (uint32_t)__cvta_generic_to_shared(smem);

    const int tid = threadIdx.x;
    const int bx = blockIdx.x, by = blockIdx.y, bz = blockIdx.z;
    const int lane = tid & 31;
    const int w  = tid >> 5;
    const int wr = w >> 2;               // 0..1
    const int wc = w & 3;                // 0..3
    const int g1 = lane >> 2;            // 0..7
    const int g2 = lane & 3;             // 0..3

    const long long aOff = (long long)bz * aB + (long long)by * BM * K;
    const long long bOff = (long long)bz * bB + (long long)bx * BN * K;
    AH += aOff; AL += aOff; BH += bOff; BL += bOff;
    C += (long long)bz * cB;

    // per-thread load coords (2 float4 slots per matrix per stage)
    const int f0 = tid, f1 = tid + 256;
    const int r0 = f0 >> 2, kg0 = (f0 & 3) * 4;
    const int r1 = f1 >> 2, kg1 = (f1 & 3) * 4;
    const uint32_t o0 = (uint32_t)(r0 * LDS_ + kg0) * 4;
    const uint32_t o1 = (uint32_t)(r1 * LDS_ + kg1) * 4;

    auto issue = [&](int stage, int k0) {
        const uint32_t uAH = ubase + stage * TILE_B;
        const uint32_t uAL = ubase + (STG + stage) * TILE_B;
        const uint32_t uBH = ubase + (2 * STG + stage) * TILE_B;
        const uint32_t uBL = ubase + (3 * STG + stage) * TILE_B;
        long long ga0 = (long long)r0 * K + k0 + kg0;
        long long ga1 = (long long)r1 * K + k0 + kg1;
        cpa16(uAH + o0, AH + ga0); cpa16(uAH + o1, AH + ga1);
        cpa16(uAL + o0, AL + ga0); cpa16(uAL + o1, AL + ga1);
        cpa16(uBH + o0, BH + ga0); cpa16(uBH + o1, BH + ga1);
        cpa16(uBL + o0, BL + ga0); cpa16(uBL + o1, BL + ga1);
    };

    float acc[4][4][4];
    #pragma unroll
    for (int i = 0; i < 4; i++)
        #pragma unroll
        for (int j = 0; j < 4; j++)
            #pragma unroll
            for (int q = 0; q < 4; q++) acc[i][j][q] = 0.f;

    const int KT = K / BK;

    issue(0, 0);
    asm volatile("cp.async.commit_group;\n");

    for (int kt = 0; kt < KT; kt++) {
        asm volatile("cp.async.wait_group 0;\n");
        __syncthreads();

        int pf = kt + 1;
        if (pf < KT) {
            issue(pf & 1, pf * BK);
            asm volatile("cp.async.commit_group;\n");
        }

        const int stage = kt & 1;
        const uint32_t* sAH = smem + stage * TILE_U32;
        const uint32_t* sAL = smem + (STG + stage) * TILE_U32;
        const uint32_t* sBH = smem + (2 * STG + stage) * TILE_U32;
        const uint32_t* sBL = smem + (3 * STG + stage) * TILE_U32;

        #pragma unroll
        for (int ks = 0; ks < BK; ks += 8) {
            const int kk = ks + g2;
            uint32_t aH[4][4], aL[4][4], bH[4][2], bL[4][2];
            #pragma unroll
            for (int mt = 0; mt < 4; mt++) {
                int m0 = wr * 64 + mt * 16 + g1;
                int i00 = m0 * LDS_ + kk, i10 = (m0 + 8) * LDS_ + kk;
                aH[mt][0] = sAH[i00];     aH[mt][1] = sAH[i10];
                aH[mt][2] = sAH[i00 + 4]; aH[mt][3] = sAH[i10 + 4];
                aL[mt][0] = sAL[i00];     aL[mt][1] = sAL[i10];
                aL[mt][2] = sAL[i00 + 4]; aL[mt][3] = sAL[i10 + 4];
            }
            #pragma unroll
            for (int nt = 0; nt < 4; nt++) {
                int n0 = (wc * 32 + nt * 8 + g1) * LDS_ + kk;
                bH[nt][0] = sBH[n0]; bH[nt][1] = sBH[n0 + 4];
                bL[nt][0] = sBL[n0]; bL[nt][1] = sBL[n0 + 4];
            }
            #pragma unroll
            for (int mt = 0; mt < 4; mt++)
                #pragma unroll
                for (int nt = 0; nt < 4; nt++) {
                    float* c = acc[mt][nt];
                    MMA_TF32(c, aH[mt][0], aH[mt][1], aH[mt][2], aH[mt][3],
                             bH[nt][0], bH[nt][1]);
                    MMA_TF32(c, aH[mt][0], aH[mt][1], aH[mt][2], aH[mt][3],
                             bL[nt][0], bL[nt][1]);
                    MMA_TF32(c, aL[mt][0], aL[mt][1], aL[mt][2], aL[mt][3],
                             bH[nt][0], bH[nt][1]);
                }
        }
    }

    // ---- epilogue: fp32 adds, float2 stores ----
    const int gr0 = by * BM + wr * 64;
    const int gc0 = bx * BN + wc * 32;
    #pragma unroll
    for (int mt = 0; mt < 4; mt++) {
        #pragma unroll
        for (int nt = 0; nt < 4; nt++) {
            int row = gr0 + mt * 16 + g1;
            int col = gc0 + nt * 8 + 2 * g2;
            long long i0 = (long long)row * N + col;
            long long i1 = (long long)(row + 8) * N + col;
            float v0 = acc[mt][nt][0], v1 = acc[mt][nt][1];
            float v2 = acc[mt][nt][2], v3 = acc[mt][nt][3];
            if (Cadd) {
                float2 u0 = *(const float2*)(Cadd + i0);
                float2 u1 = *(const float2*)(Cadd + i1);
                v0 += u0.x; v1 += u0.y; v2 += u1.x; v3 += u1.y;
            }
            if (bias1) {
                float bb0 = bias1[col] + bias2[col];
                float bb1 = bias1[col + 1] + bias2[col + 1];
                v0 += bb0; v1 += bb1; v2 += bb0; v3 += bb1;
            }
            *(float2*)(C + i0) = make_float2(v0, v1);
            *(float2*)(C + i1) = make_float2(v2, v3);
        }
    }
}

// ---------------- softmax over rows of 1024, writes tf32 hi/lo ---------------
__global__ void softmax1024_split(const float* __restrict__ s,
                                  float* __restrict__ oh, float* __restrict__ ol)
{
    __shared__ float red[8];
    const float* p = s + (size_t)blockIdx.x * NKS;
    float* ph = oh + (size_t)blockIdx.x * NKS;
    float* pl = ol + (size_t)blockIdx.x * NKS;
    const int tid = threadIdx.x;

    float v[4];
    float m = -1e30f;
    #pragma unroll
    for (int i = 0; i < 4; i++) { v[i] = p[tid + i * 256]; m = fmaxf(m, v[i]); }
    #pragma unroll
    for (int o = 16; o > 0; o >>= 1) m = fmaxf(m, __shfl_xor_sync(0xffffffffu, m, o));
    if ((tid & 31) == 0) red[tid >> 5] = m;
    __syncthreads();
    float bm = -1e30f;
    #pragma unroll
    for (int i = 0; i < 8; i++) bm = fmaxf(bm, red[i]);
    __syncthreads();

    float sum = 0.f;
    #pragma unroll
    for (int i = 0; i < 4; i++) { v[i] = __expf(v[i] - bm); sum += v[i]; }
    #pragma unroll
    for (int o = 16; o > 0; o >>= 1) sum += __shfl_xor_sync(0xffffffffu, sum, o);
    if ((tid & 31) == 0) red[tid >> 5] = sum;
    __syncthreads();
    float tot = 0.f;
    #pragma unroll
    for (int i = 0; i < 8; i++) tot += red[i];
    float inv = 1.f / tot;
    #pragma unroll
    for (int i = 0; i < 4; i++) {
        float a = v[i] * inv;
        float h, l; split2(a, h, l);
        ph[tid + i * 256] = h;
        pl[tid + i * 256] = l;
    }
}

// ---------------- fused LSTM pointwise (writes h + split) --------------------
__global__ void lstm_pw(const float* __restrict__ gates, const float* __restrict__ x,
                        const float* __restrict__ r, float* __restrict__ h,
                        float* __restrict__ c,
                        float* __restrict__ hH, float* __restrict__ hL)
{
    long long idx = (long long)blockIdx.x * blockDim.x + threadIdx.x;
    int m = (int)(idx >> 9);
    int e = (int)(idx & 511);
    const float* grow = gates + (long long)m * G4;
    float gi = grow[e];
    float gf = grow[512 + e];
    float gg = grow[1024 + e];
    float go = grow[1536 + e];
    float cp = c[idx];
    float si = 1.f / (1.f + __expf(-gi));
    float sf = 1.f / (1.f + __expf(-gf));
    float so = 1.f / (1.f + __expf(-go));
    float cn = sf * cp + si * tanhf(gg);
    float hn = so * tanhf(cn) + x[idx] + r[idx];
    c[idx] = cn;
    h[idx] = hn;
    float hh, hl; split2(hn, hh, hl);
    hH[idx] = hh;
    hL[idx] = hl;
}

// step 0: h=c=0 exactly -> gates = xW, attn uniform -> r = rmean[b]
__global__ void lstm_pw0(const float* __restrict__ xW, const float* __restrict__ x,
                         const float* __restrict__ rmean, float* __restrict__ h,
                         float* __restrict__ c,
                         float* __restrict__ hH, float* __restrict__ hL)
{
    long long idx = (long long)blockIdx.x * blockDim.x + threadIdx.x;
    int m = (int)(idx >> 9);
    int e = (int)(idx & 511);
    int b = m >> 7;                      // m = b*128 + t
    const float* grow = xW + (long long)m * G4;
    float gi = grow[e];
    float gg = grow[1024 + e];
    float go = grow[1536 + e];
    float si = 1.f / (1.f + __expf(-gi));
    float so = 1.f / (1.f + __expf(-go));
    float cn = si * tanhf(gg);           // f*c_prev = 0
    float hn = so * tanhf(cn) + x[idx] + rmean[(size_t)b * EDIM + e];
    c[idx] = cn;
    h[idx] = hn;
    float hh, hl; split2(hn, hh, hl);
    hH[idx] = hh;
    hL[idx] = hl;
}

// ---------------- launch ----------------------------------------------------
extern "C" void kernel_launch(void* const* d_in, const int* in_sizes, int n_in,
                              void* d_out, int out_size)
{
    const float* targets = (const float*)d_in[0];   // [8192, 512]
    const float* sup     = (const float*)d_in[1];   // [64, 1024, 512]
    const float* W_ih    = (const float*)d_in[2];   // [2048, 512]
    const float* W_hh    = (const float*)d_in[3];   // [2048, 512]
    const float* b_ih    = (const float*)d_in[4];   // [2048]
    const float* b_hh    = (const float*)d_in[5];   // [2048]
    float* out = (float*)d_out;

    float *xW, *gates, *h, *c, *scores, *r, *rmean;
    float *hH, *hL, *scH, *scL, *tgtH, *tgtL;
    float *WihH, *WihL, *WhhH, *WhhL, *supH, *supL, *supTH, *supTL;
    cudaGetSymbolAddress((void**)&xW, g_xW);
    cudaGetSymbolAddress((void**)&gates, g_gates);
    cudaGetSymbolAddress((void**)&h, g_h);
    cudaGetSymbolAddress((void**)&c, g_c);
    cudaGetSymbolAddress((void**)&scores, g_scores);
    cudaGetSymbolAddress((void**)&r, g_r);
    cudaGetSymbolAddress((void**)&rmean, g_rmean);
    cudaGetSymbolAddress((void**)&hH, g_hH);
    cudaGetSymbolAddress((void**)&hL, g_hL);
    cudaGetSymbolAddress((void**)&scH, g_scH);
    cudaGetSymbolAddress((void**)&scL, g_scL);
    cudaGetSymbolAddress((void**)&tgtH, g_tgtH);
    cudaGetSymbolAddress((void**)&tgtL, g_tgtL);
    cudaGetSymbolAddress((void**)&WihH, g_WihH);
    cudaGetSymbolAddress((void**)&WihL, g_WihL);
    cudaGetSymbolAddress((void**)&WhhH, g_WhhH);
    cudaGetSymbolAddress((void**)&WhhL, g_WhhL);
    cudaGetSymbolAddress((void**)&supH, g_supH);
    cudaGetSymbolAddress((void**)&supL, g_supL);
    cudaGetSymbolAddress((void**)&supTH, g_supTH);
    cudaGetSymbolAddress((void**)&supTL, g_supTL);

    cudaFuncSetAttribute(gemm_nt, cudaFuncAttributeMaxDynamicSharedMemorySize, SMEM_SZ);

    dim3 blk(256);

    // one-time operand splits + step-0 mean
    split_kernel<<<(M_ROWS * EDIM / 4) / 256, 256>>>(
        (const float4*)targets, (float4*)tgtH, (float4*)tgtL);
    split_kernel<<<(G4 * EDIM / 4) / 256, 256>>>(
        (const float4*)W_ih, (float4*)WihH, (float4*)WihL);
    split_kernel<<<(G4 * EDIM / 4) / 256, 256>>>(
        (const float4*)W_hh, (float4*)WhhH, (float4*)WhhL);
    split_kernel<<<((size_t)NBATCH * NKS * EDIM / 4) / 256, 256>>>(
        (const float4*)sup, (float4*)supH, (float4*)supL);
    transpose_split<<<dim3(EDIM / 32, NKS / 32, NBATCH), dim3(32, 8)>>>(
        sup, supTH, supTL);
    sup_mean<<<NBATCH, 256>>>(sup, rmean);

    // xW = x @ W_ih^T + b_ih + b_hh   (loop-invariant)
    gemm_nt<<<dim3(G4 / BN, M_ROWS / BM, 1), blk, SMEM_SZ>>>(
        tgtH, tgtL, WihH, WihL, xW, nullptr, b_ih, b_hh,
        G4, EDIM, 0, 0, 0);

    // step 0 fast path (h=0): gates=xW, r=rmean
    lstm_pw0<<<(M_ROWS * EDIM) / 256, 256>>>(xW, targets, rmean, h, c, hH, hL);

    for (int s = 1; s < NSTEPS; s++) {
        // gates = xW + h_prev @ W_hh^T
        gemm_nt<<<dim3(G4 / BN, M_ROWS / BM, 1), blk, SMEM_SZ>>>(
            hH, hL, WhhH, WhhL, gates, xW, nullptr, nullptr,
            G4, EDIM, 0, 0, 0);

        // scores[b] = h_prev[b] @ sup[b]^T   (batched NT)
        gemm_nt<<<dim3(NKS / BN, 1, NBATCH), blk, SMEM_SZ>>>(
            hH, hL, supH, supL, scores, nullptr, nullptr, nullptr,
            NKS, EDIM,
            (long long)128 * EDIM, (long long)NKS * EDIM, (long long)128 * NKS);

        // softmax -> split attn
        softmax1024_split<<<M_ROWS, 256>>>(scores, scH, scL);

        // r[b] = attn[b] @ supT[b]^T  (NT with B = supT: rows e, k = n)
        gemm_nt<<<dim3(EDIM / BN, 1, NBATCH), blk, SMEM_SZ>>>(
            scH, scL, supTH, supTL, r, nullptr, nullptr, nullptr,
            EDIM, NKS,
            (long long)128 * NKS, (long long)EDIM * NKS, (long long)128 * EDIM);

        // pointwise LSTM cell + residual adds (+ h split for next step)
        lstm_pw<<<(M_ROWS * EDIM) / 256, 256>>>(gates, targets, r, h, c, hH, hL);
    }

    cudaMemcpyAsync(out, h, (size_t)M_ROWS * EDIM * sizeof(float),
                    cudaMemcpyDeviceToDevice);
}